// round 11
// baseline (speedup 1.0000x reference)
#include <cuda_runtime.h>
#include <cuda_fp16.h>
#include <cstdint>

#define T_TOK 8192
#define DIM 1024
#define NEXP 16
#define TOPK 2
#define INTER 2048
#define ATOT (T_TOK * TOPK)

#define BM 128
#define BNG 128        // glu: cols per weight matrix (W1 + W3 share the B tile)
#define BND 256        // down: output cols per CTA
#define BK 32
#define STAGES 4
#define APITCH 40      // halves; 80B rows
#define BPITCH 264     // halves; 528B rows
#define A_ST_HALVES (BM * APITCH)       // 5120
#define B_ST_HALVES (BK * BPITCH)       // 8448
#define DSMEM_SZ (STAGES * (A_ST_HALVES + B_ST_HALVES) * 2)   // 108544 B
#define GATE_SMEM (DIM * 17 * 4)        // 69632 B

// ---------------- scratch (static device globals; no allocation) ----------------
__device__ __half g_xh[(size_t)T_TOK * DIM];          // 16 MB
__device__ __half g_Hh[(size_t)ATOT * INTER];         // 67 MB
__device__ __half g_W1h[(size_t)NEXP * DIM * INTER];  // 67 MB  [E][K][N]
__device__ __half g_W3h[(size_t)NEXP * DIM * INTER];  // 67 MB
__device__ __half g_W2h[(size_t)NEXP * INTER * DIM];  // 67 MB
__device__ __half g_Yp[(size_t)ATOT * DIM];           // 33.5 MB
__device__ int   g_ti[ATOT];
__device__ float g_tw[ATOT];
__device__ int   g_counts[NEXP];    // BSS-zero initially; re-zeroed by k_combine
__device__ int   g_offsets[NEXP];
__device__ int   g_cursor[NEXP];
__device__ int   g_tok[ATOT];
__device__ float g_w[ATOT];
__device__ int   g_pos[ATOT];

// ---------------- helpers ----------------
__device__ __forceinline__ uint32_t su32(const void* p) {
    return (uint32_t)__cvta_generic_to_shared(p);
}
__device__ __forceinline__ void ldsm4(uint32_t addr, unsigned* r) {
    asm volatile("ldmatrix.sync.aligned.m8n8.x4.shared.b16 {%0,%1,%2,%3}, [%4];"
                 : "=r"(r[0]), "=r"(r[1]), "=r"(r[2]), "=r"(r[3]) : "r"(addr));
}
__device__ __forceinline__ void ldsm4t(uint32_t addr, unsigned* r) {
    asm volatile("ldmatrix.sync.aligned.m8n8.x4.trans.shared.b16 {%0,%1,%2,%3}, [%4];"
                 : "=r"(r[0]), "=r"(r[1]), "=r"(r[2]), "=r"(r[3]) : "r"(addr));
}
__device__ __forceinline__ void mma16(float* c, const unsigned* a, unsigned b0, unsigned b1) {
    asm volatile(
        "mma.sync.aligned.m16n8k16.row.col.f32.f16.f16.f32 "
        "{%0,%1,%2,%3},{%4,%5,%6,%7},{%8,%9},{%0,%1,%2,%3};"
        : "+f"(c[0]), "+f"(c[1]), "+f"(c[2]), "+f"(c[3])
        : "r"(a[0]), "r"(a[1]), "r"(a[2]), "r"(a[3]), "r"(b0), "r"(b1));
}
__device__ __forceinline__ void cpa16(uint32_t saddr, const void* g) {
    asm volatile("cp.async.cg.shared.global [%0], [%1], 16;" :: "r"(saddr), "l"(g));
}
#define CP_COMMIT asm volatile("cp.async.commit_group;" ::: "memory")
#define CP_WAIT2  asm volatile("cp.async.wait_group 2;" ::: "memory")

__device__ __forceinline__ uint4 pack8(float4 a, float4 b) {
    uint4 u;
    __half2 h;
    h = __floats2half2_rn(a.x, a.y); u.x = *(unsigned*)&h;
    h = __floats2half2_rn(a.z, a.w); u.y = *(unsigned*)&h;
    h = __floats2half2_rn(b.x, b.y); u.z = *(unsigned*)&h;
    h = __floats2half2_rn(b.z, b.w); u.w = *(unsigned*)&h;
    return u;
}
__device__ __forceinline__ float silu_f(float v) {
    return v * (1.f / (1.f + __expf(-v)));
}

// ---------------- weight conversion kernels ----------------
__device__ __forceinline__ void wconv_one(const float* __restrict__ src, __half* __restrict__ dst) {
    const size_t n16 = (size_t)NEXP * DIM * INTER / 16;
    const size_t stride = (size_t)gridDim.x * blockDim.x;
    for (size_t i = (size_t)blockIdx.x * blockDim.x + threadIdx.x; i < n16; i += stride) {
        const float4* s = reinterpret_cast<const float4*>(src) + 4 * i;
        float4 a = s[0], b = s[1], c = s[2], d = s[3];
        uint4* o = reinterpret_cast<uint4*>(dst) + 2 * i;
        o[0] = pack8(a, b);
        o[1] = pack8(c, d);
    }
}
// W1 + W3 (blockIdx.y selects)
__global__ __launch_bounds__(256) void k_wconv13(const float* __restrict__ W1,
                                                 const float* __restrict__ W3) {
    wconv_one(blockIdx.y == 0 ? W1 : W3, blockIdx.y == 0 ? g_W1h : g_W3h);
}
// W2 only
__global__ __launch_bounds__(256) void k_wconv2(const float* __restrict__ W2) {
    wconv_one(W2, g_W2h);
}

// ---------------- gate: smem-cached Wg, fused x->fp16 ----------------
__global__ __launch_bounds__(256) void k_gate(const float* __restrict__ x,
                                              const float* __restrict__ Wg,
                                              const float* __restrict__ bg) {
    extern __shared__ float sWg[];   // [DIM][17] padded
    const int tid = threadIdx.x;
    for (int idx = tid; idx < DIM * NEXP; idx += 256) {
        const int d = idx >> 4, e = idx & 15;
        sWg[d * 17 + e] = Wg[idx];
    }
    __syncthreads();

    const int warp = tid >> 5, lane = tid & 31;
    const int t = blockIdx.x * 8 + warp;
    if (t >= T_TOK) return;

    float acc[NEXP];
#pragma unroll
    for (int e = 0; e < NEXP; e++) acc[e] = 0.f;
    const float* xr = x + (size_t)t * DIM;
    __half* xh = g_xh + (size_t)t * DIM;
#pragma unroll 4
    for (int i = 0; i < DIM / 32; i++) {
        const int d = i * 32 + lane;
        const float xv = xr[d];
        xh[d] = __float2half(xv);
        const float* wr = &sWg[d * 17];
#pragma unroll
        for (int e = 0; e < NEXP; e++) acc[e] += xv * wr[e];
    }
#pragma unroll
    for (int e = 0; e < NEXP; e++) {
        float v = acc[e];
#pragma unroll
        for (int o = 16; o > 0; o >>= 1) v += __shfl_xor_sync(0xffffffffu, v, o);
        acc[e] = v + bg[e];
    }
    float mx = acc[0];
#pragma unroll
    for (int e = 1; e < NEXP; e++) mx = fmaxf(mx, acc[e]);
    float p[NEXP];
#pragma unroll
    for (int e = 0; e < NEXP; e++) p[e] = __expf(acc[e] - mx);
    int i0, i1; float p0, p1;
    if (p[0] >= p[1]) { i0 = 0; p0 = p[0]; i1 = 1; p1 = p[1]; }
    else              { i0 = 1; p0 = p[1]; i1 = 0; p1 = p[0]; }
#pragma unroll
    for (int e = 2; e < NEXP; e++) {
        if (p[e] > p0)      { i1 = i0; p1 = p0; i0 = e; p0 = p[e]; }
        else if (p[e] > p1) { i1 = e; p1 = p[e]; }
    }
    if (lane == 0) {
        const float ws = p0 + p1;
        g_ti[2 * t] = i0;     g_tw[2 * t] = p0 / ws;
        g_ti[2 * t + 1] = i1; g_tw[2 * t + 1] = p1 / ws;
        atomicAdd(&g_counts[i0], 1);
        atomicAdd(&g_counts[i1], 1);
    }
}

__global__ void k_prefix() {
    int s = 0;
    for (int e = 0; e < NEXP; e++) { g_offsets[e] = s; s += g_counts[e]; }
}
__global__ void k_scatter() {
    const int t = blockIdx.x * blockDim.x + threadIdx.x;
    if (t >= T_TOK) return;
#pragma unroll
    for (int k = 0; k < TOPK; k++) {
        const int e = g_ti[2 * t + k];
        const int slot = atomicAdd(&g_cursor[e], 1);
        const int pos = g_offsets[e] + slot;
        g_tok[pos] = t;
        g_w[pos] = g_tw[2 * t + k];
        g_pos[2 * t + k] = pos;
    }
}

// ---------------- fused GLU GEMM: H = silu(xW1+b1)*(xW3+b3) ----------------
// 512 threads, tile 128 x (128+128), BK=32, 4-stage cp.async (R4 structure)
__global__ __launch_bounds__(512, 1) void k_glu(const float* __restrict__ b1,
                                                const float* __restrict__ b3) {
    const int e = blockIdx.z;
    const int cnt = g_counts[e];
    const int mt = blockIdx.x;
    if (mt * BM >= cnt) return;
    const int nt = blockIdx.y;
    const int seg = g_offsets[e];
    const int tid = threadIdx.x;
    const int wid = tid >> 5, lane = tid & 31;

    extern __shared__ __half sm[];
    __half* As = sm;                              // [STAGES][BM][APITCH]
    __half* Bs = sm + STAGES * A_ST_HALVES;       // [STAGES][BK][BPITCH]

    const int aRow = tid >> 2;
    const int aSeg = (tid & 3) * 8;
    const int grow = mt * BM + aRow;
    const int prow = seg + ((grow < cnt) ? grow : (cnt - 1));
    const __half* aptr = g_xh + (size_t)g_tok[prow] * DIM + aSeg;

    const int bK = tid >> 4;           // 0..31
    const int bSeg = (tid & 15) * 8;   // 0..120 halves
    const __half* w1p = g_W1h + (size_t)e * DIM * INTER + (size_t)bK * INTER + nt * BNG + bSeg;
    const __half* w3p = g_W3h + (size_t)e * DIM * INTER + (size_t)bK * INTER + nt * BNG + bSeg;

    const int wm = wid & 3, wn = wid >> 2;   // 4m x 4n
    const int lrow = lane & 15, lseg = (lane >> 4) * 8;
    const int g = lane >> 2, tg = lane & 3;

    float acc1[2][4][4], acc3[2][4][4];
#pragma unroll
    for (int i = 0; i < 2; i++)
#pragma unroll
        for (int j = 0; j < 4; j++)
#pragma unroll
            for (int q = 0; q < 4; q++) { acc1[i][j][q] = 0.f; acc3[i][j][q] = 0.f; }

#pragma unroll
    for (int c = 0; c < STAGES - 1; c++) {
        cpa16(su32(&As[(size_t)c * A_ST_HALVES + aRow * APITCH + aSeg]), aptr + c * BK);
        cpa16(su32(&Bs[(size_t)c * B_ST_HALVES + bK * BPITCH + bSeg]), w1p + (size_t)c * BK * INTER);
        cpa16(su32(&Bs[(size_t)c * B_ST_HALVES + bK * BPITCH + 128 + bSeg]), w3p + (size_t)c * BK * INTER);
        CP_COMMIT;
    }

    const int NKT = DIM / BK;  // 32
#pragma unroll 1
    for (int j = 0; j < NKT; j++) {
        CP_WAIT2;
        __syncthreads();
        const int st = j & (STAGES - 1);
        const __half* Ab = As + (size_t)st * A_ST_HALVES;
        const __half* Bb = Bs + (size_t)st * B_ST_HALVES;
#pragma unroll
        for (int ks = 0; ks < 2; ks++) {
            unsigned af[2][4];
#pragma unroll
            for (int mi = 0; mi < 2; mi++)
                ldsm4(su32(&Ab[(wm * 32 + mi * 16 + lrow) * APITCH + ks * 16 + lseg]), af[mi]);
#pragma unroll
            for (int nh = 0; nh < 2; nh++) {
                unsigned bf[4];
                ldsm4t(su32(&Bb[(ks * 16 + lrow) * BPITCH + wn * 32 + nh * 16 + lseg]), bf);
#pragma unroll
                for (int mi = 0; mi < 2; mi++) {
                    mma16(acc1[mi][2 * nh],     af[mi], bf[0], bf[1]);
                    mma16(acc1[mi][2 * nh + 1], af[mi], bf[2], bf[3]);
                }
            }
#pragma unroll
            for (int nh = 0; nh < 2; nh++) {
                unsigned bf[4];
                ldsm4t(su32(&Bb[(ks * 16 + lrow) * BPITCH + 128 + wn * 32 + nh * 16 + lseg]), bf);
#pragma unroll
                for (int mi = 0; mi < 2; mi++) {
                    mma16(acc3[mi][2 * nh],     af[mi], bf[0], bf[1]);
                    mma16(acc3[mi][2 * nh + 1], af[mi], bf[2], bf[3]);
                }
            }
        }
        const int nc = j + STAGES - 1;
        if (nc < NKT) {
            const int ns = nc & (STAGES - 1);
            cpa16(su32(&As[(size_t)ns * A_ST_HALVES + aRow * APITCH + aSeg]), aptr + nc * BK);
            cpa16(su32(&Bs[(size_t)ns * B_ST_HALVES + bK * BPITCH + bSeg]), w1p + (size_t)nc * BK * INTER);
            cpa16(su32(&Bs[(size_t)ns * B_ST_HALVES + bK * BPITCH + 128 + bSeg]), w3p + (size_t)nc * BK * INTER);
        }
        CP_COMMIT;
    }

    // epilogue: h = silu(v1+b1)*(v3+b3) -> fp16
#pragma unroll
    for (int mi = 0; mi < 2; mi++) {
        const int rl0 = mt * BM + wm * 32 + mi * 16 + g;
        const int rl1 = rl0 + 8;
#pragma unroll
        for (int ni = 0; ni < 4; ni++) {
            const int col = nt * BNG + wn * 32 + ni * 8 + 2 * tg;
            const float bb1x = b1[e * INTER + col], bb1y = b1[e * INTER + col + 1];
            const float bb3x = b3[e * INTER + col], bb3y = b3[e * INTER + col + 1];
            if (rl0 < cnt) {
                const float h0 = silu_f(acc1[mi][ni][0] + bb1x) * (acc3[mi][ni][0] + bb3x);
                const float h1 = silu_f(acc1[mi][ni][1] + bb1y) * (acc3[mi][ni][1] + bb3y);
                *reinterpret_cast<__half2*>(&g_Hh[(size_t)(seg + rl0) * INTER + col]) = __floats2half2_rn(h0, h1);
            }
            if (rl1 < cnt) {
                const float h0 = silu_f(acc1[mi][ni][2] + bb1x) * (acc3[mi][ni][2] + bb3x);
                const float h1 = silu_f(acc1[mi][ni][3] + bb1y) * (acc3[mi][ni][3] + bb3y);
                *reinterpret_cast<__half2*>(&g_Hh[(size_t)(seg + rl1) * INTER + col]) = __floats2half2_rn(h0, h1);
            }
        }
    }
}

// ---------------- down GEMM: Yp = (H@W2 + b2) * w  (fp16 out) ----------------
// 512 threads, tile 128 x 256, BK=32, 4-stage pipeline (R4 structure)
__global__ __launch_bounds__(512, 1) void k_down(const float* __restrict__ b2) {
    const int e = blockIdx.z;
    const int cnt = g_counts[e];
    const int mt = blockIdx.x;
    if (mt * BM >= cnt) return;
    const int nt = blockIdx.y;
    const int seg = g_offsets[e];
    const int tid = threadIdx.x;
    const int wid = tid >> 5, lane = tid & 31;

    extern __shared__ __half sm[];
    __half* As = sm;
    __half* Bs = sm + STAGES * A_ST_HALVES;

    const int aRow = tid >> 2;
    const int aSeg = (tid & 3) * 8;
    int ar = seg + mt * BM + aRow;
    if (ar > ATOT - 1) ar = ATOT - 1;
    const __half* aptr = g_Hh + (size_t)ar * INTER + aSeg;

    const int bK = tid >> 4;
    const int bSeg = (tid & 15) * 8;
    const __half* w2p = g_W2h + (size_t)e * INTER * DIM + (size_t)bK * DIM + nt * BND + bSeg;

    const int wm = wid & 3, wn = wid >> 2;   // warp tile 32x64
    const int lrow = lane & 15, lseg = (lane >> 4) * 8;
    const int g = lane >> 2, tg = lane & 3;

    float acc[2][8][4];
#pragma unroll
    for (int i = 0; i < 2; i++)
#pragma unroll
        for (int j = 0; j < 8; j++)
#pragma unroll
            for (int q = 0; q < 4; q++) acc[i][j][q] = 0.f;

#pragma unroll
    for (int c = 0; c < STAGES - 1; c++) {
        cpa16(su32(&As[(size_t)c * A_ST_HALVES + aRow * APITCH + aSeg]), aptr + c * BK);
        cpa16(su32(&Bs[(size_t)c * B_ST_HALVES + bK * BPITCH + bSeg]), w2p + (size_t)c * BK * DIM);
        cpa16(su32(&Bs[(size_t)c * B_ST_HALVES + bK * BPITCH + 128 + bSeg]), w2p + 128 + (size_t)c * BK * DIM);
        CP_COMMIT;
    }

    const int NKT = INTER / BK;  // 64
#pragma unroll 1
    for (int j = 0; j < NKT; j++) {
        CP_WAIT2;
        __syncthreads();
        const int st = j & (STAGES - 1);
        const __half* Ab = As + (size_t)st * A_ST_HALVES;
        const __half* Bb = Bs + (size_t)st * B_ST_HALVES;
#pragma unroll
        for (int ks = 0; ks < 2; ks++) {
            unsigned af[2][4];
#pragma unroll
            for (int mi = 0; mi < 2; mi++)
                ldsm4(su32(&Ab[(wm * 32 + mi * 16 + lrow) * APITCH + ks * 16 + lseg]), af[mi]);
#pragma unroll
            for (int nh = 0; nh < 4; nh++) {
                unsigned bf[4];
                ldsm4t(su32(&Bb[(ks * 16 + lrow) * BPITCH + wn * 64 + nh * 16 + lseg]), bf);
#pragma unroll
                for (int mi = 0; mi < 2; mi++) {
                    mma16(acc[mi][2 * nh],     af[mi], bf[0], bf[1]);
                    mma16(acc[mi][2 * nh + 1], af[mi], bf[2], bf[3]);
                }
            }
        }
        const int nc = j + STAGES - 1;
        if (nc < NKT) {
            const int ns = nc & (STAGES - 1);
            cpa16(su32(&As[(size_t)ns * A_ST_HALVES + aRow * APITCH + aSeg]), aptr + nc * BK);
            cpa16(su32(&Bs[(size_t)ns * B_ST_HALVES + bK * BPITCH + bSeg]), w2p + (size_t)nc * BK * DIM);
            cpa16(su32(&Bs[(size_t)ns * B_ST_HALVES + bK * BPITCH + 128 + bSeg]), w2p + 128 + (size_t)nc * BK * DIM);
        }
        CP_COMMIT;
    }

    // epilogue: weighted fp16 positional write
#pragma unroll
    for (int mi = 0; mi < 2; mi++) {
        const int rl0 = mt * BM + wm * 32 + mi * 16 + g;
        const int rl1 = rl0 + 8;
        const int p0 = seg + rl0, p1 = seg + rl1;
        const float w0 = (rl0 < cnt) ? g_w[p0] : 0.f;
        const float w1 = (rl1 < cnt) ? g_w[p1] : 0.f;
#pragma unroll
        for (int ni = 0; ni < 8; ni++) {
            const int col = nt * BND + wn * 64 + ni * 8 + 2 * tg;
            const float bbx = b2[e * DIM + col], bby = b2[e * DIM + col + 1];
            if (rl0 < cnt)
                *reinterpret_cast<__half2*>(&g_Yp[(size_t)p0 * DIM + col]) =
                    __floats2half2_rn((acc[mi][ni][0] + bbx) * w0, (acc[mi][ni][1] + bby) * w0);
            if (rl1 < cnt)
                *reinterpret_cast<__half2*>(&g_Yp[(size_t)p1 * DIM + col]) =
                    __floats2half2_rn((acc[mi][ni][2] + bbx) * w1, (acc[mi][ni][3] + bby) * w1);
        }
    }
}

// ---------------- combine: y[t] = Yp[p0] + Yp[p1]; re-zero counters ----------------
__global__ void k_combine(float* __restrict__ y) {
    const int idx = blockIdx.x * blockDim.x + threadIdx.x;
    if (idx < NEXP) { g_counts[idx] = 0; g_cursor[idx] = 0; }
    const int n4 = T_TOK * DIM / 4;
    if (idx >= n4) return;
    const int t = idx / (DIM / 4);
    const int c4 = idx % (DIM / 4);
    const int p0 = g_pos[2 * t], p1 = g_pos[2 * t + 1];
    const __half2* ra = reinterpret_cast<const __half2*>(&g_Yp[(size_t)p0 * DIM + 4 * c4]);
    const __half2* rb = reinterpret_cast<const __half2*>(&g_Yp[(size_t)p1 * DIM + 4 * c4]);
    const float2 a0 = __half22float2(ra[0]), a1 = __half22float2(ra[1]);
    const float2 b0 = __half22float2(rb[0]), b1 = __half22float2(rb[1]);
    reinterpret_cast<float4*>(y)[idx] =
        make_float4(a0.x + b0.x, a0.y + b0.y, a1.x + b1.x, a1.y + b1.y);
}

// ---------------- launch: fork weight conversion onto a side stream ----------------
extern "C" void kernel_launch(void* const* d_in, const int* in_sizes, int n_in,
                              void* d_out, int out_size) {
    const float* x  = (const float*)d_in[0];
    const float* Wg = (const float*)d_in[1];
    const float* bg = (const float*)d_in[2];
    const float* W1 = (const float*)d_in[3];
    const float* b1 = (const float*)d_in[4];
    const float* W2 = (const float*)d_in[5];
    const float* b2 = (const float*)d_in[6];
    const float* W3 = (const float*)d_in[7];
    const float* b3 = (const float*)d_in[8];
    float* y = (float*)d_out;

    // one-time setup (first call is the uncaptured correctness run)
    static cudaStream_t s2 = nullptr;
    static cudaEvent_t ev0 = nullptr, ev13 = nullptr, ev2 = nullptr;
    if (s2 == nullptr) {
        cudaStreamCreateWithFlags(&s2, cudaStreamNonBlocking);
        cudaEventCreateWithFlags(&ev0,  cudaEventDisableTiming);
        cudaEventCreateWithFlags(&ev13, cudaEventDisableTiming);
        cudaEventCreateWithFlags(&ev2,  cudaEventDisableTiming);
        cudaFuncSetAttribute(k_glu,  cudaFuncAttributeMaxDynamicSharedMemorySize, DSMEM_SZ);
        cudaFuncSetAttribute(k_down, cudaFuncAttributeMaxDynamicSharedMemorySize, DSMEM_SZ);
        cudaFuncSetAttribute(k_gate, cudaFuncAttributeMaxDynamicSharedMemorySize, GATE_SMEM);
    }

    // fork: weight conversion on s2, routing on the main stream
    cudaEventRecord(ev0, 0);
    cudaStreamWaitEvent(s2, ev0, 0);
    k_wconv13<<<dim3(2048, 2), 256, 0, s2>>>(W1, W3);
    cudaEventRecord(ev13, s2);
    k_wconv2<<<dim3(2048, 1), 256, 0, s2>>>(W2);
    cudaEventRecord(ev2, s2);

    k_gate<<<T_TOK / 8, 256, GATE_SMEM>>>(x, Wg, bg);
    k_prefix<<<1, 1>>>();
    k_scatter<<<(T_TOK + 255) / 256, 256>>>();

    // join: glu needs W1h/W3h
    cudaStreamWaitEvent(0, ev13, 0);
    dim3 gglu(T_TOK / BM, INTER / BNG, NEXP);    // (64, 16, 16), mt fastest
    k_glu<<<gglu, 512, DSMEM_SZ>>>(b1, b3);

    // join: down needs W2h
    cudaStreamWaitEvent(0, ev2, 0);
    dim3 gdown(T_TOK / BM, DIM / BND, NEXP);     // (64, 4, 16)
    k_down<<<gdown, 512, DSMEM_SZ>>>(b2);

    const int n4 = T_TOK * DIM / 4;
    k_combine<<<(n4 + 255) / 256, 256>>>(y);
}

// round 12
// speedup vs baseline: 1.0602x; 1.0602x over previous
#include <cuda_runtime.h>
#include <cuda_fp16.h>
#include <cstdint>

#define T_TOK 8192
#define DIM 1024
#define NEXP 16
#define TOPK 2
#define INTER 2048
#define ATOT (T_TOK * TOPK)

#define BM 128
#define BNG 128        // glu: cols per weight matrix (W1 + W3 share the B tile)
#define BND 256        // down: output cols per CTA
#define BK 32
#define STAGES 4
#define APITCH 40      // halves; 80B rows
#define BPITCH 264     // halves; 528B rows
#define A_ST_HALVES (BM * APITCH)       // 5120
#define B_ST_HALVES (BK * BPITCH)       // 8448
#define DSMEM_SZ (STAGES * (A_ST_HALVES + B_ST_HALVES) * 2)   // 108544 B
#define GATE_SMEM (DIM * 17 * 4)        // 69632 B
#define MAXWL 160                       // >= 128 + 16 worklist slots

// ---------------- scratch (static device globals; no allocation) ----------------
__device__ __half g_xh[(size_t)T_TOK * DIM];          // 16 MB
__device__ __half g_Hh[(size_t)ATOT * INTER];         // 67 MB
__device__ __half g_W1h[(size_t)NEXP * DIM * INTER];  // 67 MB  [E][K][N]
__device__ __half g_W3h[(size_t)NEXP * DIM * INTER];  // 67 MB
__device__ __half g_W2h[(size_t)NEXP * INTER * DIM];  // 67 MB
__device__ __half g_Yp[(size_t)ATOT * DIM];           // 33.5 MB
__device__ int   g_ti[ATOT];
__device__ float g_tw[ATOT];
__device__ int   g_counts[NEXP];    // BSS-zero initially; re-zeroed by k_combine
__device__ int   g_offsets[NEXP];
__device__ int   g_cursor[NEXP];
__device__ int   g_tok[ATOT];
__device__ float g_w[ATOT];
__device__ int   g_pos[ATOT];
__device__ int   g_wl_e[MAXWL];     // worklist: expert per tile slot
__device__ int   g_wl_mt[MAXWL];    // worklist: local m-tile per slot
__device__ int   g_nwl;             // number of occupied slots

// ---------------- helpers ----------------
__device__ __forceinline__ uint32_t su32(const void* p) {
    return (uint32_t)__cvta_generic_to_shared(p);
}
__device__ __forceinline__ void ldsm4(uint32_t addr, unsigned* r) {
    asm volatile("ldmatrix.sync.aligned.m8n8.x4.shared.b16 {%0,%1,%2,%3}, [%4];"
                 : "=r"(r[0]), "=r"(r[1]), "=r"(r[2]), "=r"(r[3]) : "r"(addr));
}
__device__ __forceinline__ void ldsm4t(uint32_t addr, unsigned* r) {
    asm volatile("ldmatrix.sync.aligned.m8n8.x4.trans.shared.b16 {%0,%1,%2,%3}, [%4];"
                 : "=r"(r[0]), "=r"(r[1]), "=r"(r[2]), "=r"(r[3]) : "r"(addr));
}
__device__ __forceinline__ void mma16(float* c, const unsigned* a, unsigned b0, unsigned b1) {
    asm volatile(
        "mma.sync.aligned.m16n8k16.row.col.f32.f16.f16.f32 "
        "{%0,%1,%2,%3},{%4,%5,%6,%7},{%8,%9},{%0,%1,%2,%3};"
        : "+f"(c[0]), "+f"(c[1]), "+f"(c[2]), "+f"(c[3])
        : "r"(a[0]), "r"(a[1]), "r"(a[2]), "r"(a[3]), "r"(b0), "r"(b1));
}
__device__ __forceinline__ void cpa16(uint32_t saddr, const void* g) {
    asm volatile("cp.async.cg.shared.global [%0], [%1], 16;" :: "r"(saddr), "l"(g));
}
#define CP_COMMIT asm volatile("cp.async.commit_group;" ::: "memory")
#define CP_WAIT2  asm volatile("cp.async.wait_group 2;" ::: "memory")

__device__ __forceinline__ uint4 pack8(float4 a, float4 b) {
    uint4 u;
    __half2 h;
    h = __floats2half2_rn(a.x, a.y); u.x = *(unsigned*)&h;
    h = __floats2half2_rn(a.z, a.w); u.y = *(unsigned*)&h;
    h = __floats2half2_rn(b.x, b.y); u.z = *(unsigned*)&h;
    h = __floats2half2_rn(b.z, b.w); u.w = *(unsigned*)&h;
    return u;
}
__device__ __forceinline__ float silu_f(float v) {
    return v * (1.f / (1.f + __expf(-v)));
}

// ---------------- fused weight conversion (W1|W3|W2 by blockIdx.y) ----------------
__global__ __launch_bounds__(256) void k_wconv3(const float* __restrict__ W1,
                                                const float* __restrict__ W3,
                                                const float* __restrict__ W2) {
    const float* src = (blockIdx.y == 0) ? W1 : (blockIdx.y == 1) ? W3 : W2;
    __half* dst = (blockIdx.y == 0) ? g_W1h : (blockIdx.y == 1) ? g_W3h : g_W2h;
    const size_t n16 = (size_t)NEXP * DIM * INTER / 16;
    const size_t stride = (size_t)gridDim.x * blockDim.x;
    for (size_t i = (size_t)blockIdx.x * blockDim.x + threadIdx.x; i < n16; i += stride) {
        const float4* s = reinterpret_cast<const float4*>(src) + 4 * i;
        float4 a = s[0], b = s[1], c = s[2], d = s[3];
        uint4* o = reinterpret_cast<uint4*>(dst) + 2 * i;
        o[0] = pack8(a, b);
        o[1] = pack8(c, d);
    }
}

// ---------------- gate: smem-cached Wg, fused x->fp16 ----------------
__global__ __launch_bounds__(256) void k_gate(const float* __restrict__ x,
                                              const float* __restrict__ Wg,
                                              const float* __restrict__ bg) {
    extern __shared__ float sWg[];   // [DIM][17] padded
    const int tid = threadIdx.x;
    for (int idx = tid; idx < DIM * NEXP; idx += 256) {
        const int d = idx >> 4, e = idx & 15;
        sWg[d * 17 + e] = Wg[idx];
    }
    __syncthreads();

    const int warp = tid >> 5, lane = tid & 31;
    const int t = blockIdx.x * 8 + warp;
    if (t >= T_TOK) return;

    float acc[NEXP];
#pragma unroll
    for (int e = 0; e < NEXP; e++) acc[e] = 0.f;
    const float* xr = x + (size_t)t * DIM;
    __half* xh = g_xh + (size_t)t * DIM;
#pragma unroll 4
    for (int i = 0; i < DIM / 32; i++) {
        const int d = i * 32 + lane;
        const float xv = xr[d];
        xh[d] = __float2half(xv);
        const float* wr = &sWg[d * 17];
#pragma unroll
        for (int e = 0; e < NEXP; e++) acc[e] += xv * wr[e];
    }
#pragma unroll
    for (int e = 0; e < NEXP; e++) {
        float v = acc[e];
#pragma unroll
        for (int o = 16; o > 0; o >>= 1) v += __shfl_xor_sync(0xffffffffu, v, o);
        acc[e] = v + bg[e];
    }
    float mx = acc[0];
#pragma unroll
    for (int e = 1; e < NEXP; e++) mx = fmaxf(mx, acc[e]);
    float p[NEXP];
#pragma unroll
    for (int e = 0; e < NEXP; e++) p[e] = __expf(acc[e] - mx);
    int i0, i1; float p0, p1;
    if (p[0] >= p[1]) { i0 = 0; p0 = p[0]; i1 = 1; p1 = p[1]; }
    else              { i0 = 1; p0 = p[1]; i1 = 0; p1 = p[0]; }
#pragma unroll
    for (int e = 2; e < NEXP; e++) {
        if (p[e] > p0)      { i1 = i0; p1 = p0; i0 = e; p0 = p[e]; }
        else if (p[e] > p1) { i1 = e; p1 = p[e]; }
    }
    if (lane == 0) {
        const float ws = p0 + p1;
        g_ti[2 * t] = i0;     g_tw[2 * t] = p0 / ws;
        g_ti[2 * t + 1] = i1; g_tw[2 * t + 1] = p1 / ws;
        atomicAdd(&g_counts[i0], 1);
        atomicAdd(&g_counts[i1], 1);
    }
}

// ---------------- prefix + worklist build ----------------
__global__ void k_prefix() {
    int s = 0, idx = 0;
    for (int e = 0; e < NEXP; e++) {
        g_offsets[e] = s;
        const int c = g_counts[e];
        s += c;
        const int ntile = (c + BM - 1) / BM;
        for (int i = 0; i < ntile; i++) {
            g_wl_e[idx] = e;
            g_wl_mt[idx] = i;
            idx++;
        }
    }
    g_nwl = idx;
}
__global__ void k_scatter() {
    const int t = blockIdx.x * blockDim.x + threadIdx.x;
    if (t >= T_TOK) return;
#pragma unroll
    for (int k = 0; k < TOPK; k++) {
        const int e = g_ti[2 * t + k];
        const int slot = atomicAdd(&g_cursor[e], 1);
        const int pos = g_offsets[e] + slot;
        g_tok[pos] = t;
        g_w[pos] = g_tw[2 * t + k];
        g_pos[2 * t + k] = pos;
    }
}

// ---------------- fused GLU GEMM: H = silu(xW1+b1)*(xW3+b3) ----------------
// 512 threads, tile 128 x (128+128), BK=32, 4-stage cp.async; worklist-indexed grid
__global__ __launch_bounds__(512, 1) void k_glu(const float* __restrict__ b1,
                                                const float* __restrict__ b3) {
    const int slot = blockIdx.x;
    if (slot >= g_nwl) return;
    const int e = g_wl_e[slot];
    const int mt = g_wl_mt[slot];
    const int cnt = g_counts[e];
    const int nt = blockIdx.y;
    const int seg = g_offsets[e];
    const int tid = threadIdx.x;
    const int wid = tid >> 5, lane = tid & 31;

    extern __shared__ __half sm[];
    __half* As = sm;                              // [STAGES][BM][APITCH]
    __half* Bs = sm + STAGES * A_ST_HALVES;       // [STAGES][BK][BPITCH]

    const int aRow = tid >> 2;
    const int aSeg = (tid & 3) * 8;
    const int grow = mt * BM + aRow;
    const int prow = seg + ((grow < cnt) ? grow : (cnt - 1));
    const __half* aptr = g_xh + (size_t)g_tok[prow] * DIM + aSeg;

    const int bK = tid >> 4;           // 0..31
    const int bSeg = (tid & 15) * 8;   // 0..120 halves
    const __half* w1p = g_W1h + (size_t)e * DIM * INTER + (size_t)bK * INTER + nt * BNG + bSeg;
    const __half* w3p = g_W3h + (size_t)e * DIM * INTER + (size_t)bK * INTER + nt * BNG + bSeg;

    const int wm = wid & 3, wn = wid >> 2;   // 4m x 4n
    const int lrow = lane & 15, lseg = (lane >> 4) * 8;
    const int g = lane >> 2, tg = lane & 3;

    float acc1[2][4][4], acc3[2][4][4];
#pragma unroll
    for (int i = 0; i < 2; i++)
#pragma unroll
        for (int j = 0; j < 4; j++)
#pragma unroll
            for (int q = 0; q < 4; q++) { acc1[i][j][q] = 0.f; acc3[i][j][q] = 0.f; }

#pragma unroll
    for (int c = 0; c < STAGES - 1; c++) {
        cpa16(su32(&As[(size_t)c * A_ST_HALVES + aRow * APITCH + aSeg]), aptr + c * BK);
        cpa16(su32(&Bs[(size_t)c * B_ST_HALVES + bK * BPITCH + bSeg]), w1p + (size_t)c * BK * INTER);
        cpa16(su32(&Bs[(size_t)c * B_ST_HALVES + bK * BPITCH + 128 + bSeg]), w3p + (size_t)c * BK * INTER);
        CP_COMMIT;
    }

    const int NKT = DIM / BK;  // 32
#pragma unroll 1
    for (int j = 0; j < NKT; j++) {
        CP_WAIT2;
        __syncthreads();
        const int st = j & (STAGES - 1);
        const __half* Ab = As + (size_t)st * A_ST_HALVES;
        const __half* Bb = Bs + (size_t)st * B_ST_HALVES;
#pragma unroll
        for (int ks = 0; ks < 2; ks++) {
            unsigned af[2][4];
#pragma unroll
            for (int mi = 0; mi < 2; mi++)
                ldsm4(su32(&Ab[(wm * 32 + mi * 16 + lrow) * APITCH + ks * 16 + lseg]), af[mi]);
#pragma unroll
            for (int nh = 0; nh < 2; nh++) {
                unsigned bf[4];
                ldsm4t(su32(&Bb[(ks * 16 + lrow) * BPITCH + wn * 32 + nh * 16 + lseg]), bf);
#pragma unroll
                for (int mi = 0; mi < 2; mi++) {
                    mma16(acc1[mi][2 * nh],     af[mi], bf[0], bf[1]);
                    mma16(acc1[mi][2 * nh + 1], af[mi], bf[2], bf[3]);
                }
            }
#pragma unroll
            for (int nh = 0; nh < 2; nh++) {
                unsigned bf[4];
                ldsm4t(su32(&Bb[(ks * 16 + lrow) * BPITCH + 128 + wn * 32 + nh * 16 + lseg]), bf);
#pragma unroll
                for (int mi = 0; mi < 2; mi++) {
                    mma16(acc3[mi][2 * nh],     af[mi], bf[0], bf[1]);
                    mma16(acc3[mi][2 * nh + 1], af[mi], bf[2], bf[3]);
                }
            }
        }
        const int nc = j + STAGES - 1;
        if (nc < NKT) {
            const int ns = nc & (STAGES - 1);
            cpa16(su32(&As[(size_t)ns * A_ST_HALVES + aRow * APITCH + aSeg]), aptr + nc * BK);
            cpa16(su32(&Bs[(size_t)ns * B_ST_HALVES + bK * BPITCH + bSeg]), w1p + (size_t)nc * BK * INTER);
            cpa16(su32(&Bs[(size_t)ns * B_ST_HALVES + bK * BPITCH + 128 + bSeg]), w3p + (size_t)nc * BK * INTER);
        }
        CP_COMMIT;
    }

    // epilogue: h = silu(v1+b1)*(v3+b3) -> fp16
#pragma unroll
    for (int mi = 0; mi < 2; mi++) {
        const int rl0 = mt * BM + wm * 32 + mi * 16 + g;
        const int rl1 = rl0 + 8;
#pragma unroll
        for (int ni = 0; ni < 4; ni++) {
            const int col = nt * BNG + wn * 32 + ni * 8 + 2 * tg;
            const float bb1x = b1[e * INTER + col], bb1y = b1[e * INTER + col + 1];
            const float bb3x = b3[e * INTER + col], bb3y = b3[e * INTER + col + 1];
            if (rl0 < cnt) {
                const float h0 = silu_f(acc1[mi][ni][0] + bb1x) * (acc3[mi][ni][0] + bb3x);
                const float h1 = silu_f(acc1[mi][ni][1] + bb1y) * (acc3[mi][ni][1] + bb3y);
                *reinterpret_cast<__half2*>(&g_Hh[(size_t)(seg + rl0) * INTER + col]) = __floats2half2_rn(h0, h1);
            }
            if (rl1 < cnt) {
                const float h0 = silu_f(acc1[mi][ni][2] + bb1x) * (acc3[mi][ni][2] + bb3x);
                const float h1 = silu_f(acc1[mi][ni][3] + bb1y) * (acc3[mi][ni][3] + bb3y);
                *reinterpret_cast<__half2*>(&g_Hh[(size_t)(seg + rl1) * INTER + col]) = __floats2half2_rn(h0, h1);
            }
        }
    }
}

// ---------------- down GEMM: Yp = (H@W2 + b2) * w  (fp16 out) ----------------
// 512 threads, tile 128 x 256, BK=32, 4-stage pipeline; worklist-indexed grid
__global__ __launch_bounds__(512, 1) void k_down(const float* __restrict__ b2) {
    const int slot = blockIdx.x;
    if (slot >= g_nwl) return;
    const int e = g_wl_e[slot];
    const int mt = g_wl_mt[slot];
    const int cnt = g_counts[e];
    const int nt = blockIdx.y;
    const int seg = g_offsets[e];
    const int tid = threadIdx.x;
    const int wid = tid >> 5, lane = tid & 31;

    extern __shared__ __half sm[];
    __half* As = sm;
    __half* Bs = sm + STAGES * A_ST_HALVES;

    const int aRow = tid >> 2;
    const int aSeg = (tid & 3) * 8;
    int ar = seg + mt * BM + aRow;
    if (ar > ATOT - 1) ar = ATOT - 1;
    const __half* aptr = g_Hh + (size_t)ar * INTER + aSeg;

    const int bK = tid >> 4;
    const int bSeg = (tid & 15) * 8;
    const __half* w2p = g_W2h + (size_t)e * INTER * DIM + (size_t)bK * DIM + nt * BND + bSeg;

    const int wm = wid & 3, wn = wid >> 2;   // warp tile 32x64
    const int lrow = lane & 15, lseg = (lane >> 4) * 8;
    const int g = lane >> 2, tg = lane & 3;

    float acc[2][8][4];
#pragma unroll
    for (int i = 0; i < 2; i++)
#pragma unroll
        for (int j = 0; j < 8; j++)
#pragma unroll
            for (int q = 0; q < 4; q++) acc[i][j][q] = 0.f;

#pragma unroll
    for (int c = 0; c < STAGES - 1; c++) {
        cpa16(su32(&As[(size_t)c * A_ST_HALVES + aRow * APITCH + aSeg]), aptr + c * BK);
        cpa16(su32(&Bs[(size_t)c * B_ST_HALVES + bK * BPITCH + bSeg]), w2p + (size_t)c * BK * DIM);
        cpa16(su32(&Bs[(size_t)c * B_ST_HALVES + bK * BPITCH + 128 + bSeg]), w2p + 128 + (size_t)c * BK * DIM);
        CP_COMMIT;
    }

    const int NKT = INTER / BK;  // 64
#pragma unroll 1
    for (int j = 0; j < NKT; j++) {
        CP_WAIT2;
        __syncthreads();
        const int st = j & (STAGES - 1);
        const __half* Ab = As + (size_t)st * A_ST_HALVES;
        const __half* Bb = Bs + (size_t)st * B_ST_HALVES;
#pragma unroll
        for (int ks = 0; ks < 2; ks++) {
            unsigned af[2][4];
#pragma unroll
            for (int mi = 0; mi < 2; mi++)
                ldsm4(su32(&Ab[(wm * 32 + mi * 16 + lrow) * APITCH + ks * 16 + lseg]), af[mi]);
#pragma unroll
            for (int nh = 0; nh < 4; nh++) {
                unsigned bf[4];
                ldsm4t(su32(&Bb[(ks * 16 + lrow) * BPITCH + wn * 64 + nh * 16 + lseg]), bf);
#pragma unroll
                for (int mi = 0; mi < 2; mi++) {
                    mma16(acc[mi][2 * nh],     af[mi], bf[0], bf[1]);
                    mma16(acc[mi][2 * nh + 1], af[mi], bf[2], bf[3]);
                }
            }
        }
        const int nc = j + STAGES - 1;
        if (nc < NKT) {
            const int ns = nc & (STAGES - 1);
            cpa16(su32(&As[(size_t)ns * A_ST_HALVES + aRow * APITCH + aSeg]), aptr + nc * BK);
            cpa16(su32(&Bs[(size_t)ns * B_ST_HALVES + bK * BPITCH + bSeg]), w2p + (size_t)nc * BK * DIM);
            cpa16(su32(&Bs[(size_t)ns * B_ST_HALVES + bK * BPITCH + 128 + bSeg]), w2p + 128 + (size_t)nc * BK * DIM);
        }
        CP_COMMIT;
    }

    // epilogue: weighted fp16 positional write
#pragma unroll
    for (int mi = 0; mi < 2; mi++) {
        const int rl0 = mt * BM + wm * 32 + mi * 16 + g;
        const int rl1 = rl0 + 8;
        const int p0 = seg + rl0, p1 = seg + rl1;
        const float w0 = (rl0 < cnt) ? g_w[p0] : 0.f;
        const float w1 = (rl1 < cnt) ? g_w[p1] : 0.f;
#pragma unroll
        for (int ni = 0; ni < 8; ni++) {
            const int col = nt * BND + wn * 64 + ni * 8 + 2 * tg;
            const float bbx = b2[e * DIM + col], bby = b2[e * DIM + col + 1];
            if (rl0 < cnt)
                *reinterpret_cast<__half2*>(&g_Yp[(size_t)p0 * DIM + col]) =
                    __floats2half2_rn((acc[mi][ni][0] + bbx) * w0, (acc[mi][ni][1] + bby) * w0);
            if (rl1 < cnt)
                *reinterpret_cast<__half2*>(&g_Yp[(size_t)p1 * DIM + col]) =
                    __floats2half2_rn((acc[mi][ni][2] + bbx) * w1, (acc[mi][ni][3] + bby) * w1);
        }
    }
}

// ---------------- combine: y[t] = Yp[p0] + Yp[p1]; re-zero counters ----------------
__global__ void k_combine(float* __restrict__ y) {
    const int idx = blockIdx.x * blockDim.x + threadIdx.x;
    if (idx < NEXP) { g_counts[idx] = 0; g_cursor[idx] = 0; }
    const int n4 = T_TOK * DIM / 4;
    if (idx >= n4) return;
    const int t = idx / (DIM / 4);
    const int c4 = idx % (DIM / 4);
    const int p0 = g_pos[2 * t], p1 = g_pos[2 * t + 1];
    const __half2* ra = reinterpret_cast<const __half2*>(&g_Yp[(size_t)p0 * DIM + 4 * c4]);
    const __half2* rb = reinterpret_cast<const __half2*>(&g_Yp[(size_t)p1 * DIM + 4 * c4]);
    const float2 a0 = __half22float2(ra[0]), a1 = __half22float2(ra[1]);
    const float2 b0 = __half22float2(rb[0]), b1 = __half22float2(rb[1]);
    reinterpret_cast<float4*>(y)[idx] =
        make_float4(a0.x + b0.x, a0.y + b0.y, a1.x + b1.x, a1.y + b1.y);
}

// ---------------- launch (serial; overlap proved zero-sum in R11) ----------------
extern "C" void kernel_launch(void* const* d_in, const int* in_sizes, int n_in,
                              void* d_out, int out_size) {
    const float* x  = (const float*)d_in[0];
    const float* Wg = (const float*)d_in[1];
    const float* bg = (const float*)d_in[2];
    const float* W1 = (const float*)d_in[3];
    const float* b1 = (const float*)d_in[4];
    const float* W2 = (const float*)d_in[5];
    const float* b2 = (const float*)d_in[6];
    const float* W3 = (const float*)d_in[7];
    const float* b3 = (const float*)d_in[8];
    float* y = (float*)d_out;

    cudaFuncSetAttribute(k_glu,  cudaFuncAttributeMaxDynamicSharedMemorySize, DSMEM_SZ);
    cudaFuncSetAttribute(k_down, cudaFuncAttributeMaxDynamicSharedMemorySize, DSMEM_SZ);
    cudaFuncSetAttribute(k_gate, cudaFuncAttributeMaxDynamicSharedMemorySize, GATE_SMEM);

    k_wconv3<<<dim3(2048, 3), 256>>>(W1, W3, W2);
    k_gate<<<T_TOK / 8, 256, GATE_SMEM>>>(x, Wg, bg);
    k_prefix<<<1, 1>>>();
    k_scatter<<<(T_TOK + 255) / 256, 256>>>();

    dim3 gglu(144, INTER / BNG);    // (144 worklist slots, 16 nt)
    k_glu<<<gglu, 512, DSMEM_SZ>>>(b1, b3);

    dim3 gdown(144, DIM / BND);     // (144 worklist slots, 4 nt)
    k_down<<<gdown, 512, DSMEM_SZ>>>(b2);

    const int n4 = T_TOK * DIM / 4;
    k_combine<<<(n4 + 255) / 256, 256>>>(y);
}

// round 14
// speedup vs baseline: 1.0766x; 1.0154x over previous
#include <cuda_runtime.h>
#include <cuda_fp16.h>
#include <cstdint>

#define T_TOK 8192
#define DIM 1024
#define NEXP 16
#define TOPK 2
#define INTER 2048
#define ATOT (T_TOK * TOPK)

#define BM 128
#define BNG 128        // glu: cols per weight matrix (W1 + W3 share the B tile)
#define BND 256        // down: output cols per CTA
#define BK 32
#define STAGES 4
#define APITCH 40      // halves; 80B rows
#define BPITCH 264     // halves; 528B rows
#define A_ST_HALVES (BM * APITCH)       // 5120
#define B_ST_HALVES (BK * BPITCH)       // 8448
#define DSMEM_SZ (STAGES * (A_ST_HALVES + B_ST_HALVES) * 2)   // 108544 B
#define GATE_SMEM (DIM * 17 * 4)        // 69632 B
#define MAXWL 160                       // >= 128 + 16 worklist slots
#define NT_GLU (INTER / BNG)            // 16
#define NT_DOWN (DIM / BND)             // 4

// ---------------- scratch (static device globals; no allocation) ----------------
__device__ __half g_xh[(size_t)T_TOK * DIM];          // 16 MB
__device__ __half g_Hh[(size_t)ATOT * INTER];         // 67 MB
__device__ __half g_W1h[(size_t)NEXP * DIM * INTER];  // 67 MB  [E][K][N]
__device__ __half g_W3h[(size_t)NEXP * DIM * INTER];  // 67 MB
__device__ __half g_W2h[(size_t)NEXP * INTER * DIM];  // 67 MB
__device__ __half g_Yp[(size_t)ATOT * DIM];           // 33.5 MB
__device__ int   g_ti[ATOT];
__device__ float g_tw[ATOT];
__device__ int   g_counts[NEXP];    // BSS-zero initially; re-zeroed by k_combine
__device__ int   g_offsets[NEXP];
__device__ int   g_cursor[NEXP];
__device__ int   g_tok[ATOT];
__device__ float g_w[ATOT];
__device__ int   g_pos[ATOT];
__device__ int   g_wl_e[MAXWL];     // worklist: expert per tile slot
__device__ int   g_wl_mt[MAXWL];    // worklist: local m-tile per slot
__device__ int   g_nwl;             // number of occupied slots
__device__ int   g_uc_glu;          // persistent unit counter (glu)
__device__ int   g_uc_down;         // persistent unit counter (down)

// ---------------- helpers ----------------
__device__ __forceinline__ uint32_t su32(const void* p) {
    return (uint32_t)__cvta_generic_to_shared(p);
}
__device__ __forceinline__ void ldsm4(uint32_t addr, unsigned* r) {
    asm volatile("ldmatrix.sync.aligned.m8n8.x4.shared.b16 {%0,%1,%2,%3}, [%4];"
                 : "=r"(r[0]), "=r"(r[1]), "=r"(r[2]), "=r"(r[3]) : "r"(addr));
}
__device__ __forceinline__ void ldsm4t(uint32_t addr, unsigned* r) {
    asm volatile("ldmatrix.sync.aligned.m8n8.x4.trans.shared.b16 {%0,%1,%2,%3}, [%4];"
                 : "=r"(r[0]), "=r"(r[1]), "=r"(r[2]), "=r"(r[3]) : "r"(addr));
}
__device__ __forceinline__ void mma16(float* c, const unsigned* a, unsigned b0, unsigned b1) {
    asm volatile(
        "mma.sync.aligned.m16n8k16.row.col.f32.f16.f16.f32 "
        "{%0,%1,%2,%3},{%4,%5,%6,%7},{%8,%9},{%0,%1,%2,%3};"
        : "+f"(c[0]), "+f"(c[1]), "+f"(c[2]), "+f"(c[3])
        : "r"(a[0]), "r"(a[1]), "r"(a[2]), "r"(a[3]), "r"(b0), "r"(b1));
}
__device__ __forceinline__ void cpa16(uint32_t saddr, const void* g) {
    asm volatile("cp.async.cg.shared.global [%0], [%1], 16;" :: "r"(saddr), "l"(g));
}
#define CP_COMMIT asm volatile("cp.async.commit_group;" ::: "memory")
#define CP_WAIT2  asm volatile("cp.async.wait_group 2;" ::: "memory")

__device__ __forceinline__ uint4 pack8(float4 a, float4 b) {
    uint4 u;
    __half2 h;
    h = __floats2half2_rn(a.x, a.y); u.x = *(unsigned*)&h;
    h = __floats2half2_rn(a.z, a.w); u.y = *(unsigned*)&h;
    h = __floats2half2_rn(b.x, b.y); u.z = *(unsigned*)&h;
    h = __floats2half2_rn(b.z, b.w); u.w = *(unsigned*)&h;
    return u;
}
__device__ __forceinline__ float silu_f(float v) {
    return v * (1.f / (1.f + __expf(-v)));
}

// ---------------- fused weight conversion (W1|W3|W2 by blockIdx.y) ----------------
__global__ __launch_bounds__(256) void k_wconv3(const float* __restrict__ W1,
                                                const float* __restrict__ W3,
                                                const float* __restrict__ W2) {
    const float* src = (blockIdx.y == 0) ? W1 : (blockIdx.y == 1) ? W3 : W2;
    __half* dst = (blockIdx.y == 0) ? g_W1h : (blockIdx.y == 1) ? g_W3h : g_W2h;
    const size_t n16 = (size_t)NEXP * DIM * INTER / 16;
    const size_t stride = (size_t)gridDim.x * blockDim.x;
    for (size_t i = (size_t)blockIdx.x * blockDim.x + threadIdx.x; i < n16; i += stride) {
        const float4* s = reinterpret_cast<const float4*>(src) + 4 * i;
        float4 a = s[0], b = s[1], c = s[2], d = s[3];
        uint4* o = reinterpret_cast<uint4*>(dst) + 2 * i;
        o[0] = pack8(a, b);
        o[1] = pack8(c, d);
    }
}

// ---------------- gate: smem-cached Wg, fused x->fp16 ----------------
__global__ __launch_bounds__(256) void k_gate(const float* __restrict__ x,
                                              const float* __restrict__ Wg,
                                              const float* __restrict__ bg) {
    extern __shared__ float sWg[];   // [DIM][17] padded
    const int tid = threadIdx.x;
    for (int idx = tid; idx < DIM * NEXP; idx += 256) {
        const int d = idx >> 4, e = idx & 15;
        sWg[d * 17 + e] = Wg[idx];
    }
    __syncthreads();

    const int warp = tid >> 5, lane = tid & 31;
    const int t = blockIdx.x * 8 + warp;
    if (t >= T_TOK) return;

    float acc[NEXP];
#pragma unroll
    for (int e = 0; e < NEXP; e++) acc[e] = 0.f;
    const float* xr = x + (size_t)t * DIM;
    __half* xh = g_xh + (size_t)t * DIM;
#pragma unroll 4
    for (int i = 0; i < DIM / 32; i++) {
        const int d = i * 32 + lane;
        const float xv = xr[d];
        xh[d] = __float2half(xv);
        const float* wr = &sWg[d * 17];
#pragma unroll
        for (int e = 0; e < NEXP; e++) acc[e] += xv * wr[e];
    }
#pragma unroll
    for (int e = 0; e < NEXP; e++) {
        float v = acc[e];
#pragma unroll
        for (int o = 16; o > 0; o >>= 1) v += __shfl_xor_sync(0xffffffffu, v, o);
        acc[e] = v + bg[e];
    }
    float mx = acc[0];
#pragma unroll
    for (int e = 1; e < NEXP; e++) mx = fmaxf(mx, acc[e]);
    float p[NEXP];
#pragma unroll
    for (int e = 0; e < NEXP; e++) p[e] = __expf(acc[e] - mx);
    int i0, i1; float p0, p1;
    if (p[0] >= p[1]) { i0 = 0; p0 = p[0]; i1 = 1; p1 = p[1]; }
    else              { i0 = 1; p0 = p[1]; i1 = 0; p1 = p[0]; }
#pragma unroll
    for (int e = 2; e < NEXP; e++) {
        if (p[e] > p0)      { i1 = i0; p1 = p0; i0 = e; p0 = p[e]; }
        else if (p[e] > p1) { i1 = e; p1 = p[e]; }
    }
    if (lane == 0) {
        const float ws = p0 + p1;
        g_ti[2 * t] = i0;     g_tw[2 * t] = p0 / ws;
        g_ti[2 * t + 1] = i1; g_tw[2 * t + 1] = p1 / ws;
        atomicAdd(&g_counts[i0], 1);
        atomicAdd(&g_counts[i1], 1);
    }
}

// ---------------- prefix + worklist build + counter reset ----------------
__global__ void k_prefix() {
    int s = 0, idx = 0;
    for (int e = 0; e < NEXP; e++) {
        g_offsets[e] = s;
        const int c = g_counts[e];
        s += c;
        const int ntile = (c + BM - 1) / BM;
        for (int i = 0; i < ntile; i++) {
            g_wl_e[idx] = e;
            g_wl_mt[idx] = i;
            idx++;
        }
    }
    g_nwl = idx;
    g_uc_glu = 0;
    g_uc_down = 0;
}
__global__ void k_scatter() {
    const int t = blockIdx.x * blockDim.x + threadIdx.x;
    if (t >= T_TOK) return;
#pragma unroll
    for (int k = 0; k < TOPK; k++) {
        const int e = g_ti[2 * t + k];
        const int slot = atomicAdd(&g_cursor[e], 1);
        const int pos = g_offsets[e] + slot;
        g_tok[pos] = t;
        g_w[pos] = g_tw[2 * t + k];
        g_pos[2 * t + k] = pos;
    }
}

// ---------------- fused GLU GEMM (persistent): H = silu(xW1+b1)*(xW3+b3) ----------------
__global__ __launch_bounds__(512, 1) void k_glu(const float* __restrict__ b1,
                                                const float* __restrict__ b3) {
    extern __shared__ __half sm[];
    __half* As = sm;                              // [STAGES][BM][APITCH]
    __half* Bs = sm + STAGES * A_ST_HALVES;       // [STAGES][BK][BPITCH]
    __shared__ int s_u;

    const int tid = threadIdx.x;
    const int wid = tid >> 5, lane = tid & 31;
    const int wm = wid & 3, wn = wid >> 2;   // 4m x 4n
    const int lrow = lane & 15, lseg = (lane >> 4) * 8;
    const int g = lane >> 2, tg = lane & 3;
    const int aRow = tid >> 2;
    const int aSeg = (tid & 3) * 8;
    const int bK = tid >> 4;           // 0..31
    const int bSeg = (tid & 15) * 8;   // 0..120 halves

    for (;;) {
        if (tid == 0) s_u = atomicAdd(&g_uc_glu, 1);
        __syncthreads();
        const int u = s_u;
        const int nwl = g_nwl;
        if (u >= NT_GLU * nwl) return;
        const int nt = u / nwl;
        const int slot = u - nt * nwl;
        const int e = g_wl_e[slot];
        const int mt = g_wl_mt[slot];
        const int cnt = g_counts[e];
        const int seg = g_offsets[e];

        const int grow = mt * BM + aRow;
        const int prow = seg + ((grow < cnt) ? grow : (cnt - 1));
        const __half* aptr = g_xh + (size_t)g_tok[prow] * DIM + aSeg;
        const __half* w1p = g_W1h + (size_t)e * DIM * INTER + (size_t)bK * INTER + nt * BNG + bSeg;
        const __half* w3p = g_W3h + (size_t)e * DIM * INTER + (size_t)bK * INTER + nt * BNG + bSeg;

        float acc1[2][4][4], acc3[2][4][4];
#pragma unroll
        for (int i = 0; i < 2; i++)
#pragma unroll
            for (int j = 0; j < 4; j++)
#pragma unroll
                for (int q = 0; q < 4; q++) { acc1[i][j][q] = 0.f; acc3[i][j][q] = 0.f; }

#pragma unroll
        for (int c = 0; c < STAGES - 1; c++) {
            cpa16(su32(&As[(size_t)c * A_ST_HALVES + aRow * APITCH + aSeg]), aptr + c * BK);
            cpa16(su32(&Bs[(size_t)c * B_ST_HALVES + bK * BPITCH + bSeg]), w1p + (size_t)c * BK * INTER);
            cpa16(su32(&Bs[(size_t)c * B_ST_HALVES + bK * BPITCH + 128 + bSeg]), w3p + (size_t)c * BK * INTER);
            CP_COMMIT;
        }

        const int NKT = DIM / BK;  // 32
#pragma unroll 1
        for (int j = 0; j < NKT; j++) {
            CP_WAIT2;
            __syncthreads();
            const int st = j & (STAGES - 1);
            const __half* Ab = As + (size_t)st * A_ST_HALVES;
            const __half* Bb = Bs + (size_t)st * B_ST_HALVES;
#pragma unroll
            for (int ks = 0; ks < 2; ks++) {
                unsigned af[2][4];
#pragma unroll
                for (int mi = 0; mi < 2; mi++)
                    ldsm4(su32(&Ab[(wm * 32 + mi * 16 + lrow) * APITCH + ks * 16 + lseg]), af[mi]);
#pragma unroll
                for (int nh = 0; nh < 2; nh++) {
                    unsigned bf[4];
                    ldsm4t(su32(&Bb[(ks * 16 + lrow) * BPITCH + wn * 32 + nh * 16 + lseg]), bf);
#pragma unroll
                    for (int mi = 0; mi < 2; mi++) {
                        mma16(acc1[mi][2 * nh],     af[mi], bf[0], bf[1]);
                        mma16(acc1[mi][2 * nh + 1], af[mi], bf[2], bf[3]);
                    }
                }
#pragma unroll
                for (int nh = 0; nh < 2; nh++) {
                    unsigned bf[4];
                    ldsm4t(su32(&Bb[(ks * 16 + lrow) * BPITCH + 128 + wn * 32 + nh * 16 + lseg]), bf);
#pragma unroll
                    for (int mi = 0; mi < 2; mi++) {
                        mma16(acc3[mi][2 * nh],     af[mi], bf[0], bf[1]);
                        mma16(acc3[mi][2 * nh + 1], af[mi], bf[2], bf[3]);
                    }
                }
            }
            const int nc = j + STAGES - 1;
            if (nc < NKT) {
                const int ns = nc & (STAGES - 1);
                cpa16(su32(&As[(size_t)ns * A_ST_HALVES + aRow * APITCH + aSeg]), aptr + nc * BK);
                cpa16(su32(&Bs[(size_t)ns * B_ST_HALVES + bK * BPITCH + bSeg]), w1p + (size_t)nc * BK * INTER);
                cpa16(su32(&Bs[(size_t)ns * B_ST_HALVES + bK * BPITCH + 128 + bSeg]), w3p + (size_t)nc * BK * INTER);
            }
            CP_COMMIT;
        }

        // epilogue: h = silu(v1+b1)*(v3+b3) -> fp16
#pragma unroll
        for (int mi = 0; mi < 2; mi++) {
            const int rl0 = mt * BM + wm * 32 + mi * 16 + g;
            const int rl1 = rl0 + 8;
#pragma unroll
            for (int ni = 0; ni < 4; ni++) {
                const int col = nt * BNG + wn * 32 + ni * 8 + 2 * tg;
                const float bb1x = b1[e * INTER + col], bb1y = b1[e * INTER + col + 1];
                const float bb3x = b3[e * INTER + col], bb3y = b3[e * INTER + col + 1];
                if (rl0 < cnt) {
                    const float h0 = silu_f(acc1[mi][ni][0] + bb1x) * (acc3[mi][ni][0] + bb3x);
                    const float h1 = silu_f(acc1[mi][ni][1] + bb1y) * (acc3[mi][ni][1] + bb3y);
                    *reinterpret_cast<__half2*>(&g_Hh[(size_t)(seg + rl0) * INTER + col]) = __floats2half2_rn(h0, h1);
                }
                if (rl1 < cnt) {
                    const float h0 = silu_f(acc1[mi][ni][2] + bb1x) * (acc3[mi][ni][2] + bb3x);
                    const float h1 = silu_f(acc1[mi][ni][3] + bb1y) * (acc3[mi][ni][3] + bb3y);
                    *reinterpret_cast<__half2*>(&g_Hh[(size_t)(seg + rl1) * INTER + col]) = __floats2half2_rn(h0, h1);
                }
            }
        }
    }
}

// ---------------- down GEMM (persistent): Yp = (H@W2 + b2) * w  (fp16 out) ----------------
__global__ __launch_bounds__(512, 1) void k_down(const float* __restrict__ b2) {
    extern __shared__ __half sm[];
    __half* As = sm;
    __half* Bs = sm + STAGES * A_ST_HALVES;
    __shared__ int s_u;

    const int tid = threadIdx.x;
    const int wid = tid >> 5, lane = tid & 31;
    const int wm = wid & 3, wn = wid >> 2;   // warp tile 32x64
    const int lrow = lane & 15, lseg = (lane >> 4) * 8;
    const int g = lane >> 2, tg = lane & 3;
    const int aRow = tid >> 2;
    const int aSeg = (tid & 3) * 8;
    const int bK = tid >> 4;
    const int bSeg = (tid & 15) * 8;

    for (;;) {
        if (tid == 0) s_u = atomicAdd(&g_uc_down, 1);
        __syncthreads();
        const int u = s_u;
        const int nwl = g_nwl;
        if (u >= NT_DOWN * nwl) return;
        const int nt = u / nwl;
        const int slot = u - nt * nwl;
        const int e = g_wl_e[slot];
        const int mt = g_wl_mt[slot];
        const int cnt = g_counts[e];
        const int seg = g_offsets[e];

        int ar = seg + mt * BM + aRow;
        if (ar > ATOT - 1) ar = ATOT - 1;
        const __half* aptr = g_Hh + (size_t)ar * INTER + aSeg;
        const __half* w2p = g_W2h + (size_t)e * INTER * DIM + (size_t)bK * DIM + nt * BND + bSeg;

        float acc[2][8][4];
#pragma unroll
        for (int i = 0; i < 2; i++)
#pragma unroll
            for (int j = 0; j < 8; j++)
#pragma unroll
                for (int q = 0; q < 4; q++) acc[i][j][q] = 0.f;

#pragma unroll
        for (int c = 0; c < STAGES - 1; c++) {
            cpa16(su32(&As[(size_t)c * A_ST_HALVES + aRow * APITCH + aSeg]), aptr + c * BK);
            cpa16(su32(&Bs[(size_t)c * B_ST_HALVES + bK * BPITCH + bSeg]), w2p + (size_t)c * BK * DIM);
            cpa16(su32(&Bs[(size_t)c * B_ST_HALVES + bK * BPITCH + 128 + bSeg]), w2p + 128 + (size_t)c * BK * DIM);
            CP_COMMIT;
        }

        const int NKT = INTER / BK;  // 64
#pragma unroll 1
        for (int j = 0; j < NKT; j++) {
            CP_WAIT2;
            __syncthreads();
            const int st = j & (STAGES - 1);
            const __half* Ab = As + (size_t)st * A_ST_HALVES;
            const __half* Bb = Bs + (size_t)st * B_ST_HALVES;
#pragma unroll
            for (int ks = 0; ks < 2; ks++) {
                unsigned af[2][4];
#pragma unroll
                for (int mi = 0; mi < 2; mi++)
                    ldsm4(su32(&Ab[(wm * 32 + mi * 16 + lrow) * APITCH + ks * 16 + lseg]), af[mi]);
#pragma unroll
                for (int nh = 0; nh < 4; nh++) {
                    unsigned bf[4];
                    ldsm4t(su32(&Bb[(ks * 16 + lrow) * BPITCH + wn * 64 + nh * 16 + lseg]), bf);
#pragma unroll
                    for (int mi = 0; mi < 2; mi++) {
                        mma16(acc[mi][2 * nh],     af[mi], bf[0], bf[1]);
                        mma16(acc[mi][2 * nh + 1], af[mi], bf[2], bf[3]);
                    }
                }
            }
            const int nc = j + STAGES - 1;
            if (nc < NKT) {
                const int ns = nc & (STAGES - 1);
                cpa16(su32(&As[(size_t)ns * A_ST_HALVES + aRow * APITCH + aSeg]), aptr + nc * BK);
                cpa16(su32(&Bs[(size_t)ns * B_ST_HALVES + bK * BPITCH + bSeg]), w2p + (size_t)nc * BK * DIM);
                cpa16(su32(&Bs[(size_t)ns * B_ST_HALVES + bK * BPITCH + 128 + bSeg]), w2p + 128 + (size_t)nc * BK * DIM);
            }
            CP_COMMIT;
        }

        // epilogue: weighted fp16 positional write
#pragma unroll
        for (int mi = 0; mi < 2; mi++) {
            const int rl0 = mt * BM + wm * 32 + mi * 16 + g;
            const int rl1 = rl0 + 8;
            const int p0 = seg + rl0, p1 = seg + rl1;
            const float w0 = (rl0 < cnt) ? g_w[p0] : 0.f;
            const float w1 = (rl1 < cnt) ? g_w[p1] : 0.f;
#pragma unroll
            for (int ni = 0; ni < 8; ni++) {
                const int col = nt * BND + wn * 64 + ni * 8 + 2 * tg;
                const float bbx = b2[e * DIM + col], bby = b2[e * DIM + col + 1];
                if (rl0 < cnt)
                    *reinterpret_cast<__half2*>(&g_Yp[(size_t)p0 * DIM + col]) =
                        __floats2half2_rn((acc[mi][ni][0] + bbx) * w0, (acc[mi][ni][1] + bby) * w0);
                if (rl1 < cnt)
                    *reinterpret_cast<__half2*>(&g_Yp[(size_t)p1 * DIM + col]) =
                        __floats2half2_rn((acc[mi][ni][2] + bbx) * w1, (acc[mi][ni][3] + bby) * w1);
            }
        }
    }
}

// ---------------- combine: y[t] = Yp[p0] + Yp[p1]; re-zero counters ----------------
__global__ void k_combine(float* __restrict__ y) {
    const int idx = blockIdx.x * blockDim.x + threadIdx.x;
    if (idx < NEXP) { g_counts[idx] = 0; g_cursor[idx] = 0; }
    const int n4 = T_TOK * DIM / 4;
    if (idx >= n4) return;
    const int t = idx / (DIM / 4);
    const int c4 = idx % (DIM / 4);
    const int p0 = g_pos[2 * t], p1 = g_pos[2 * t + 1];
    const __half2* ra = reinterpret_cast<const __half2*>(&g_Yp[(size_t)p0 * DIM + 4 * c4]);
    const __half2* rb = reinterpret_cast<const __half2*>(&g_Yp[(size_t)p1 * DIM + 4 * c4]);
    const float2 a0 = __half22float2(ra[0]), a1 = __half22float2(ra[1]);
    const float2 b0 = __half22float2(rb[0]), b1 = __half22float2(rb[1]);
    reinterpret_cast<float4*>(y)[idx] =
        make_float4(a0.x + b0.x, a0.y + b0.y, a1.x + b1.x, a1.y + b1.y);
}

// ---------------- launch ----------------
extern "C" void kernel_launch(void* const* d_in, const int* in_sizes, int n_in,
                              void* d_out, int out_size) {
    const float* x  = (const float*)d_in[0];
    const float* Wg = (const float*)d_in[1];
    const float* bg = (const float*)d_in[2];
    const float* W1 = (const float*)d_in[3];
    const float* b1 = (const float*)d_in[4];
    const float* W2 = (const float*)d_in[5];
    const float* b2 = (const float*)d_in[6];
    const float* W3 = (const float*)d_in[7];
    const float* b3 = (const float*)d_in[8];
    float* y = (float*)d_out;

    cudaFuncSetAttribute(k_glu,  cudaFuncAttributeMaxDynamicSharedMemorySize, DSMEM_SZ);
    cudaFuncSetAttribute(k_down, cudaFuncAttributeMaxDynamicSharedMemorySize, DSMEM_SZ);
    cudaFuncSetAttribute(k_gate, cudaFuncAttributeMaxDynamicSharedMemorySize, GATE_SMEM);

    k_wconv3<<<dim3(2048, 3), 256>>>(W1, W3, W2);
    k_gate<<<T_TOK / 8, 256, GATE_SMEM>>>(x, Wg, bg);
    k_prefix<<<1, 1>>>();
    k_scatter<<<(T_TOK + 255) / 256, 256>>>();

    k_glu<<<148, 512, DSMEM_SZ>>>(b1, b3);     // persistent
    k_down<<<148, 512, DSMEM_SZ>>>(b2);        // persistent

    const int n4 = T_TOK * DIM / 4;
    k_combine<<<(n4 + 255) / 256, 256>>>(y);
}

// round 15
// speedup vs baseline: 1.1004x; 1.0222x over previous
#include <cuda_runtime.h>
#include <cuda_fp16.h>
#include <cstdint>

#define T_TOK 8192
#define DIM 1024
#define NEXP 16
#define TOPK 2
#define INTER 2048
#define ATOT (T_TOK * TOPK)

#define BM 128
#define BNG 128        // glu: cols per weight matrix (W1 + W3 share the B tile)
#define BND 256        // down: output cols per CTA
#define BK 32
#define STAGES 4
#define APITCH 40      // halves; 80B rows
#define BPITCH 264     // halves; 528B rows
#define A_ST_HALVES (BM * APITCH)       // 5120
#define B_ST_HALVES (BK * BPITCH)       // 8448
#define DSMEM_SZ (STAGES * (A_ST_HALVES + B_ST_HALVES) * 2)   // 108544 B
#define GATE_SMEM (DIM * 17 * 4)        // 69632 B
#define MAXWL 160                       // >= 128 + 16 worklist slots
#define GATE_BLOCKS (T_TOK / 8)         // 1024

// ---------------- scratch (static device globals; no allocation) ----------------
__device__ __half g_xh[(size_t)T_TOK * DIM];          // 16 MB
__device__ __half g_Hh[(size_t)ATOT * INTER];         // 67 MB
__device__ __half g_W1h[(size_t)NEXP * DIM * INTER];  // 67 MB  [E][K][N]
__device__ __half g_W3h[(size_t)NEXP * DIM * INTER];  // 67 MB
__device__ __half g_W2h[(size_t)NEXP * INTER * DIM];  // 67 MB
__device__ __half g_Yp[(size_t)ATOT * DIM];           // 33.5 MB
__device__ int   g_ti[ATOT];
__device__ float g_tw[ATOT];
__device__ int   g_counts[NEXP];    // BSS-zero initially; re-zeroed by k_combine
__device__ int   g_offsets[NEXP];
__device__ int   g_cursor[NEXP];
__device__ int   g_tok[ATOT];
__device__ float g_w[ATOT];
__device__ int   g_pos[ATOT];
__device__ int   g_wl_e[MAXWL];     // worklist: expert per tile slot
__device__ int   g_wl_mt[MAXWL];    // worklist: local m-tile per slot
__device__ int   g_nwl;             // number of occupied slots
__device__ int   g_uc;              // persistent unit counter (glu then down)
__device__ int   g_done[MAXWL];     // per-slot glu completion count
__device__ int   g_gate_done;       // gate block completion ticket

// ---------------- helpers ----------------
__device__ __forceinline__ uint32_t su32(const void* p) {
    return (uint32_t)__cvta_generic_to_shared(p);
}
__device__ __forceinline__ void ldsm4(uint32_t addr, unsigned* r) {
    asm volatile("ldmatrix.sync.aligned.m8n8.x4.shared.b16 {%0,%1,%2,%3}, [%4];"
                 : "=r"(r[0]), "=r"(r[1]), "=r"(r[2]), "=r"(r[3]) : "r"(addr));
}
__device__ __forceinline__ void ldsm4t(uint32_t addr, unsigned* r) {
    asm volatile("ldmatrix.sync.aligned.m8n8.x4.trans.shared.b16 {%0,%1,%2,%3}, [%4];"
                 : "=r"(r[0]), "=r"(r[1]), "=r"(r[2]), "=r"(r[3]) : "r"(addr));
}
__device__ __forceinline__ void mma16(float* c, const unsigned* a, unsigned b0, unsigned b1) {
    asm volatile(
        "mma.sync.aligned.m16n8k16.row.col.f32.f16.f16.f32 "
        "{%0,%1,%2,%3},{%4,%5,%6,%7},{%8,%9},{%0,%1,%2,%3};"
        : "+f"(c[0]), "+f"(c[1]), "+f"(c[2]), "+f"(c[3])
        : "r"(a[0]), "r"(a[1]), "r"(a[2]), "r"(a[3]), "r"(b0), "r"(b1));
}
__device__ __forceinline__ void cpa16(uint32_t saddr, const void* g) {
    asm volatile("cp.async.cg.shared.global [%0], [%1], 16;" :: "r"(saddr), "l"(g));
}
#define CP_COMMIT asm volatile("cp.async.commit_group;" ::: "memory")
#define CP_WAIT2  asm volatile("cp.async.wait_group 2;" ::: "memory")

__device__ __forceinline__ uint4 pack8(float4 a, float4 b) {
    uint4 u;
    __half2 h;
    h = __floats2half2_rn(a.x, a.y); u.x = *(unsigned*)&h;
    h = __floats2half2_rn(a.z, a.w); u.y = *(unsigned*)&h;
    h = __floats2half2_rn(b.x, b.y); u.z = *(unsigned*)&h;
    h = __floats2half2_rn(b.z, b.w); u.w = *(unsigned*)&h;
    return u;
}
__device__ __forceinline__ float silu_f(float v) {
    return v * (1.f / (1.f + __expf(-v)));
}

// ---------------- fused weight conversion (W1|W3|W2 by blockIdx.y) ----------------
__global__ __launch_bounds__(256) void k_wconv3(const float* __restrict__ W1,
                                                const float* __restrict__ W3,
                                                const float* __restrict__ W2) {
    const float* src = (blockIdx.y == 0) ? W1 : (blockIdx.y == 1) ? W3 : W2;
    __half* dst = (blockIdx.y == 0) ? g_W1h : (blockIdx.y == 1) ? g_W3h : g_W2h;
    const size_t n16 = (size_t)NEXP * DIM * INTER / 16;
    const size_t stride = (size_t)gridDim.x * blockDim.x;
    for (size_t i = (size_t)blockIdx.x * blockDim.x + threadIdx.x; i < n16; i += stride) {
        const float4* s = reinterpret_cast<const float4*>(src) + 4 * i;
        float4 a = s[0], b = s[1], c = s[2], d = s[3];
        uint4* o = reinterpret_cast<uint4*>(dst) + 2 * i;
        o[0] = pack8(a, b);
        o[1] = pack8(c, d);
    }
}

// ---------------- gate: smem-cached Wg, fused x->fp16; last block builds worklist ----------------
__global__ __launch_bounds__(256) void k_gate(const float* __restrict__ x,
                                              const float* __restrict__ Wg,
                                              const float* __restrict__ bg) {
    extern __shared__ float sWg[];   // [DIM][17] padded
    const int tid = threadIdx.x;
    for (int idx = tid; idx < DIM * NEXP; idx += 256) {
        const int d = idx >> 4, e = idx & 15;
        sWg[d * 17 + e] = Wg[idx];
    }
    __syncthreads();

    const int warp = tid >> 5, lane = tid & 31;
    const int t = blockIdx.x * 8 + warp;
    if (t < T_TOK) {
        float acc[NEXP];
#pragma unroll
        for (int e = 0; e < NEXP; e++) acc[e] = 0.f;
        const float* xr = x + (size_t)t * DIM;
        __half* xh = g_xh + (size_t)t * DIM;
#pragma unroll 4
        for (int i = 0; i < DIM / 32; i++) {
            const int d = i * 32 + lane;
            const float xv = xr[d];
            xh[d] = __float2half(xv);
            const float* wr = &sWg[d * 17];
#pragma unroll
            for (int e = 0; e < NEXP; e++) acc[e] += xv * wr[e];
        }
#pragma unroll
        for (int e = 0; e < NEXP; e++) {
            float v = acc[e];
#pragma unroll
            for (int o = 16; o > 0; o >>= 1) v += __shfl_xor_sync(0xffffffffu, v, o);
            acc[e] = v + bg[e];
        }
        float mx = acc[0];
#pragma unroll
        for (int e = 1; e < NEXP; e++) mx = fmaxf(mx, acc[e]);
        float p[NEXP];
#pragma unroll
        for (int e = 0; e < NEXP; e++) p[e] = __expf(acc[e] - mx);
        int i0, i1; float p0, p1;
        if (p[0] >= p[1]) { i0 = 0; p0 = p[0]; i1 = 1; p1 = p[1]; }
        else              { i0 = 1; p0 = p[1]; i1 = 0; p1 = p[0]; }
#pragma unroll
        for (int e = 2; e < NEXP; e++) {
            if (p[e] > p0)      { i1 = i0; p1 = p0; i0 = e; p0 = p[e]; }
            else if (p[e] > p1) { i1 = e; p1 = p[e]; }
        }
        if (lane == 0) {
            const float ws = p0 + p1;
            g_ti[2 * t] = i0;     g_tw[2 * t] = p0 / ws;
            g_ti[2 * t + 1] = i1; g_tw[2 * t + 1] = p1 / ws;
            atomicAdd(&g_counts[i0], 1);
            atomicAdd(&g_counts[i1], 1);
        }
    }
    // last-finishing block builds prefix + worklist + resets GEMM counters
    __syncthreads();
    if (tid == 0) {
        __threadfence();
        const int ticket = atomicAdd(&g_gate_done, 1);
        if (ticket == GATE_BLOCKS - 1) {
            int s = 0, idx = 0;
            for (int e = 0; e < NEXP; e++) {
                g_offsets[e] = s;
                const int c = g_counts[e];
                s += c;
                const int ntile = (c + BM - 1) / BM;
                for (int i = 0; i < ntile; i++) {
                    g_wl_e[idx] = e;
                    g_wl_mt[idx] = i;
                    idx++;
                }
            }
            g_nwl = idx;
            g_uc = 0;
            for (int i = 0; i < MAXWL; i++) g_done[i] = 0;
            __threadfence();
        }
    }
}

__global__ void k_scatter() {
    const int t = blockIdx.x * blockDim.x + threadIdx.x;
    if (t >= T_TOK) return;
#pragma unroll
    for (int k = 0; k < TOPK; k++) {
        const int e = g_ti[2 * t + k];
        const int slot = atomicAdd(&g_cursor[e], 1);
        const int pos = g_offsets[e] + slot;
        g_tok[pos] = t;
        g_w[pos] = g_tw[2 * t + k];
        g_pos[2 * t + k] = pos;
    }
}

// ---------------- merged persistent GEMM: glu units then down units ----------------
// glu unit u in [0, 16*nwl): slot = u>>4, nt = u&15 (slot-major -> slots finish early)
// down unit v in [0, 4*nwl):  slot = v>>2, nt = v&3; spins until g_done[slot]==16
__global__ __launch_bounds__(512, 1) void k_moe(const float* __restrict__ b1,
                                                const float* __restrict__ b3,
                                                const float* __restrict__ b2) {
    extern __shared__ __half sm[];
    __half* As = sm;                              // [STAGES][BM][APITCH]
    __half* Bs = sm + STAGES * A_ST_HALVES;       // [STAGES][BK][BPITCH]
    __shared__ int s_u;

    const int tid = threadIdx.x;
    const int wid = tid >> 5, lane = tid & 31;
    const int wm = wid & 3, wn = wid >> 2;
    const int lrow = lane & 15, lseg = (lane >> 4) * 8;
    const int g = lane >> 2, tg = lane & 3;
    const int aRow = tid >> 2;
    const int aSeg = (tid & 3) * 8;
    const int bK = tid >> 4;           // 0..31
    const int bSeg = (tid & 15) * 8;   // 0..120 halves

    const int nwl = g_nwl;
    const int UG = nwl << 4;           // glu units
    const int UT = UG + (nwl << 2);    // total units

    for (;;) {
        if (tid == 0) {
            int u = atomicAdd(&g_uc, 1);
            if (u >= UG && u < UT) {
                const int slot = (u - UG) >> 2;
                while (atomicAdd(&g_done[slot], 0) < 16) { __nanosleep(64); }
                __threadfence();
            }
            s_u = u;
        }
        __syncthreads();
        const int u = s_u;
        if (u >= UT) return;

        if (u < UG) {
            // ---------------- GLU unit ----------------
            const int slot = u >> 4;
            const int nt = u & 15;
            const int e = g_wl_e[slot];
            const int mt = g_wl_mt[slot];
            const int cnt = g_counts[e];
            const int seg = g_offsets[e];

            const int grow = mt * BM + aRow;
            const int prow = seg + ((grow < cnt) ? grow : (cnt - 1));
            const __half* aptr = g_xh + (size_t)g_tok[prow] * DIM + aSeg;
            const __half* w1p = g_W1h + (size_t)e * DIM * INTER + (size_t)bK * INTER + nt * BNG + bSeg;
            const __half* w3p = g_W3h + (size_t)e * DIM * INTER + (size_t)bK * INTER + nt * BNG + bSeg;

            float acc1[2][4][4], acc3[2][4][4];
#pragma unroll
            for (int i = 0; i < 2; i++)
#pragma unroll
                for (int j = 0; j < 4; j++)
#pragma unroll
                    for (int q = 0; q < 4; q++) { acc1[i][j][q] = 0.f; acc3[i][j][q] = 0.f; }

#pragma unroll
            for (int c = 0; c < STAGES - 1; c++) {
                cpa16(su32(&As[(size_t)c * A_ST_HALVES + aRow * APITCH + aSeg]), aptr + c * BK);
                cpa16(su32(&Bs[(size_t)c * B_ST_HALVES + bK * BPITCH + bSeg]), w1p + (size_t)c * BK * INTER);
                cpa16(su32(&Bs[(size_t)c * B_ST_HALVES + bK * BPITCH + 128 + bSeg]), w3p + (size_t)c * BK * INTER);
                CP_COMMIT;
            }

            const int NKT = DIM / BK;  // 32
#pragma unroll 1
            for (int j = 0; j < NKT; j++) {
                CP_WAIT2;
                __syncthreads();
                const int st = j & (STAGES - 1);
                const __half* Ab = As + (size_t)st * A_ST_HALVES;
                const __half* Bb = Bs + (size_t)st * B_ST_HALVES;
#pragma unroll
                for (int ks = 0; ks < 2; ks++) {
                    unsigned af[2][4];
#pragma unroll
                    for (int mi = 0; mi < 2; mi++)
                        ldsm4(su32(&Ab[(wm * 32 + mi * 16 + lrow) * APITCH + ks * 16 + lseg]), af[mi]);
#pragma unroll
                    for (int nh = 0; nh < 2; nh++) {
                        unsigned bf[4];
                        ldsm4t(su32(&Bb[(ks * 16 + lrow) * BPITCH + wn * 32 + nh * 16 + lseg]), bf);
#pragma unroll
                        for (int mi = 0; mi < 2; mi++) {
                            mma16(acc1[mi][2 * nh],     af[mi], bf[0], bf[1]);
                            mma16(acc1[mi][2 * nh + 1], af[mi], bf[2], bf[3]);
                        }
                    }
#pragma unroll
                    for (int nh = 0; nh < 2; nh++) {
                        unsigned bf[4];
                        ldsm4t(su32(&Bb[(ks * 16 + lrow) * BPITCH + 128 + wn * 32 + nh * 16 + lseg]), bf);
#pragma unroll
                        for (int mi = 0; mi < 2; mi++) {
                            mma16(acc3[mi][2 * nh],     af[mi], bf[0], bf[1]);
                            mma16(acc3[mi][2 * nh + 1], af[mi], bf[2], bf[3]);
                        }
                    }
                }
                const int nc = j + STAGES - 1;
                if (nc < NKT) {
                    const int ns = nc & (STAGES - 1);
                    cpa16(su32(&As[(size_t)ns * A_ST_HALVES + aRow * APITCH + aSeg]), aptr + nc * BK);
                    cpa16(su32(&Bs[(size_t)ns * B_ST_HALVES + bK * BPITCH + bSeg]), w1p + (size_t)nc * BK * INTER);
                    cpa16(su32(&Bs[(size_t)ns * B_ST_HALVES + bK * BPITCH + 128 + bSeg]), w3p + (size_t)nc * BK * INTER);
                }
                CP_COMMIT;
            }

#pragma unroll
            for (int mi = 0; mi < 2; mi++) {
                const int rl0 = mt * BM + wm * 32 + mi * 16 + g;
                const int rl1 = rl0 + 8;
#pragma unroll
                for (int ni = 0; ni < 4; ni++) {
                    const int col = nt * BNG + wn * 32 + ni * 8 + 2 * tg;
                    const float bb1x = b1[e * INTER + col], bb1y = b1[e * INTER + col + 1];
                    const float bb3x = b3[e * INTER + col], bb3y = b3[e * INTER + col + 1];
                    if (rl0 < cnt) {
                        const float h0 = silu_f(acc1[mi][ni][0] + bb1x) * (acc3[mi][ni][0] + bb3x);
                        const float h1 = silu_f(acc1[mi][ni][1] + bb1y) * (acc3[mi][ni][1] + bb3y);
                        *reinterpret_cast<__half2*>(&g_Hh[(size_t)(seg + rl0) * INTER + col]) = __floats2half2_rn(h0, h1);
                    }
                    if (rl1 < cnt) {
                        const float h0 = silu_f(acc1[mi][ni][2] + bb1x) * (acc3[mi][ni][2] + bb3x);
                        const float h1 = silu_f(acc1[mi][ni][3] + bb1y) * (acc3[mi][ni][3] + bb3y);
                        *reinterpret_cast<__half2*>(&g_Hh[(size_t)(seg + rl1) * INTER + col]) = __floats2half2_rn(h0, h1);
                    }
                }
            }
            // signal slot progress
            __syncthreads();
            if (tid == 0) {
                __threadfence();
                atomicAdd(&g_done[slot], 1);
            }
        } else {
            // ---------------- DOWN unit ----------------
            const int v = u - UG;
            const int slot = v >> 2;
            const int nt = v & 3;
            const int e = g_wl_e[slot];
            const int mt = g_wl_mt[slot];
            const int cnt = g_counts[e];
            const int seg = g_offsets[e];

            int ar = seg + mt * BM + aRow;
            if (ar > ATOT - 1) ar = ATOT - 1;
            const __half* aptr = g_Hh + (size_t)ar * INTER + aSeg;
            const __half* w2p = g_W2h + (size_t)e * INTER * DIM + (size_t)bK * DIM + nt * BND + bSeg;

            float acc[2][8][4];
#pragma unroll
            for (int i = 0; i < 2; i++)
#pragma unroll
                for (int j = 0; j < 8; j++)
#pragma unroll
                    for (int q = 0; q < 4; q++) acc[i][j][q] = 0.f;

#pragma unroll
            for (int c = 0; c < STAGES - 1; c++) {
                cpa16(su32(&As[(size_t)c * A_ST_HALVES + aRow * APITCH + aSeg]), aptr + c * BK);
                cpa16(su32(&Bs[(size_t)c * B_ST_HALVES + bK * BPITCH + bSeg]), w2p + (size_t)c * BK * DIM);
                cpa16(su32(&Bs[(size_t)c * B_ST_HALVES + bK * BPITCH + 128 + bSeg]), w2p + 128 + (size_t)c * BK * DIM);
                CP_COMMIT;
            }

            const int NKT = INTER / BK;  // 64
#pragma unroll 1
            for (int j = 0; j < NKT; j++) {
                CP_WAIT2;
                __syncthreads();
                const int st = j & (STAGES - 1);
                const __half* Ab = As + (size_t)st * A_ST_HALVES;
                const __half* Bb = Bs + (size_t)st * B_ST_HALVES;
#pragma unroll
                for (int ks = 0; ks < 2; ks++) {
                    unsigned af[2][4];
#pragma unroll
                    for (int mi = 0; mi < 2; mi++)
                        ldsm4(su32(&Ab[(wm * 32 + mi * 16 + lrow) * APITCH + ks * 16 + lseg]), af[mi]);
#pragma unroll
                    for (int nh = 0; nh < 4; nh++) {
                        unsigned bf[4];
                        ldsm4t(su32(&Bb[(ks * 16 + lrow) * BPITCH + wn * 64 + nh * 16 + lseg]), bf);
#pragma unroll
                        for (int mi = 0; mi < 2; mi++) {
                            mma16(acc[mi][2 * nh],     af[mi], bf[0], bf[1]);
                            mma16(acc[mi][2 * nh + 1], af[mi], bf[2], bf[3]);
                        }
                    }
                }
                const int nc = j + STAGES - 1;
                if (nc < NKT) {
                    const int ns = nc & (STAGES - 1);
                    cpa16(su32(&As[(size_t)ns * A_ST_HALVES + aRow * APITCH + aSeg]), aptr + nc * BK);
                    cpa16(su32(&Bs[(size_t)ns * B_ST_HALVES + bK * BPITCH + bSeg]), w2p + (size_t)nc * BK * DIM);
                    cpa16(su32(&Bs[(size_t)ns * B_ST_HALVES + bK * BPITCH + 128 + bSeg]), w2p + 128 + (size_t)nc * BK * DIM);
                }
                CP_COMMIT;
            }

#pragma unroll
            for (int mi = 0; mi < 2; mi++) {
                const int rl0 = mt * BM + wm * 32 + mi * 16 + g;
                const int rl1 = rl0 + 8;
                const int p0 = seg + rl0, p1 = seg + rl1;
                const float w0 = (rl0 < cnt) ? g_w[p0] : 0.f;
                const float w1 = (rl1 < cnt) ? g_w[p1] : 0.f;
#pragma unroll
                for (int ni = 0; ni < 8; ni++) {
                    const int col = nt * BND + wn * 64 + ni * 8 + 2 * tg;
                    const float bbx = b2[e * DIM + col], bby = b2[e * DIM + col + 1];
                    if (rl0 < cnt)
                        *reinterpret_cast<__half2*>(&g_Yp[(size_t)p0 * DIM + col]) =
                            __floats2half2_rn((acc[mi][ni][0] + bbx) * w0, (acc[mi][ni][1] + bby) * w0);
                    if (rl1 < cnt)
                        *reinterpret_cast<__half2*>(&g_Yp[(size_t)p1 * DIM + col]) =
                            __floats2half2_rn((acc[mi][ni][2] + bbx) * w1, (acc[mi][ni][3] + bby) * w1);
                }
            }
            __syncthreads();   // smem safe for next unit's prologue
        }
    }
}

// ---------------- combine: y[t] = Yp[p0] + Yp[p1]; reset per-run state ----------------
__global__ void k_combine(float* __restrict__ y) {
    const int idx = blockIdx.x * blockDim.x + threadIdx.x;
    if (idx < NEXP) { g_counts[idx] = 0; g_cursor[idx] = 0; }
    if (idx == NEXP) g_gate_done = 0;
    const int n4 = T_TOK * DIM / 4;
    if (idx >= n4) return;
    const int t = idx / (DIM / 4);
    const int c4 = idx % (DIM / 4);
    const int p0 = g_pos[2 * t], p1 = g_pos[2 * t + 1];
    const __half2* ra = reinterpret_cast<const __half2*>(&g_Yp[(size_t)p0 * DIM + 4 * c4]);
    const __half2* rb = reinterpret_cast<const __half2*>(&g_Yp[(size_t)p1 * DIM + 4 * c4]);
    const float2 a0 = __half22float2(ra[0]), a1 = __half22float2(ra[1]);
    const float2 b0 = __half22float2(rb[0]), b1 = __half22float2(rb[1]);
    reinterpret_cast<float4*>(y)[idx] =
        make_float4(a0.x + b0.x, a0.y + b0.y, a1.x + b1.x, a1.y + b1.y);
}

// ---------------- launch ----------------
extern "C" void kernel_launch(void* const* d_in, const int* in_sizes, int n_in,
                              void* d_out, int out_size) {
    const float* x  = (const float*)d_in[0];
    const float* Wg = (const float*)d_in[1];
    const float* bg = (const float*)d_in[2];
    const float* W1 = (const float*)d_in[3];
    const float* b1 = (const float*)d_in[4];
    const float* W2 = (const float*)d_in[5];
    const float* b2 = (const float*)d_in[6];
    const float* W3 = (const float*)d_in[7];
    const float* b3 = (const float*)d_in[8];
    float* y = (float*)d_out;

    cudaFuncSetAttribute(k_moe,  cudaFuncAttributeMaxDynamicSharedMemorySize, DSMEM_SZ);
    cudaFuncSetAttribute(k_gate, cudaFuncAttributeMaxDynamicSharedMemorySize, GATE_SMEM);

    k_wconv3<<<dim3(2048, 3), 256>>>(W1, W3, W2);
    k_gate<<<GATE_BLOCKS, 256, GATE_SMEM>>>(x, Wg, bg);
    k_scatter<<<(T_TOK + 255) / 256, 256>>>();

    k_moe<<<148, 512, DSMEM_SZ>>>(b1, b3, b2);   // persistent: glu then down

    const int n4 = T_TOK * DIM / 4;
    k_combine<<<(n4 + 255) / 256, 256>>>(y);
}